// round 6
// baseline (speedup 1.0000x reference)
#include <cuda_runtime.h>

#define HH 256
#define WW 256
#define KK 64
#define MV 16
#define NSTEPS 64
#define VOLR 256.0f
#define DTST (1.0f/256.0f)

// Channel-interleaved template [k][z][y][x] -> float4 (4 MB, L2-resident)
__device__ float4 g_tmpl[KK * MV * MV * MV];
// Per-prim params: [0..8] R row-major, [9..11] pos (normalized), [12..14] scale, [15] pad
__device__ float g_prim[KK * 16];

// Blocks 0..1023: repack template. Block 1024: prep prim params.
__global__ void pack_prep_kernel(const float* __restrict__ primrgba,
                                 const float* __restrict__ primpos,
                                 const float* __restrict__ primrot,
                                 const float* __restrict__ primscale) {
    int b = blockIdx.x;
    if (b < 1024) {
        int idx = b * 256 + threadIdx.x;
        int k = idx >> 12;
        int v = idx & 4095;
        const float* base = primrgba + (size_t)k * 4 * 4096 + v;
        float4 val;
        val.x = base[0];
        val.y = base[4096];
        val.z = base[8192];
        val.w = base[12288];
        g_tmpl[idx] = val;
    } else {
        int k = threadIdx.x;
        if (k >= KK) return;
        float* P = g_prim + k * 16;
#pragma unroll
        for (int i = 0; i < 9; i++) P[i] = primrot[k * 9 + i];
        P[9]  = primpos[k * 3 + 0] / VOLR;
        P[10] = primpos[k * 3 + 1] / VOLR;
        P[11] = primpos[k * 3 + 2] / VOLR;
        P[12] = primscale[k * 3 + 0];
        P[13] = primscale[k * 3 + 1];
        P[14] = primscale[k * 3 + 2];
        P[15] = 0.f;
    }
}

// Full per-point evaluation (R3 inner loop): transform + inside test + trilinear gather.
__device__ __forceinline__ void eval_prim(
    const float* __restrict__ P, int k,
    float px, float py, float pz, float s[4])
{
    float rx = px - P[9], ry = py - P[10], rz = pz - P[11];
    float lx = (rx * P[0] + ry * P[3] + rz * P[6]) * P[12];
    float ly = (rx * P[1] + ry * P[4] + rz * P[7]) * P[13];
    float lz = (rx * P[2] + ry * P[5] + rz * P[8]) * P[14];
    if (!(fabsf(lx) < 1.0f && fabsf(ly) < 1.0f && fabsf(lz) < 1.0f)) return;

    float gx = fminf((lx + 1.0f) * 7.5f, 14.99999f);
    float gy = fminf((ly + 1.0f) * 7.5f, 14.99999f);
    float gz = fminf((lz + 1.0f) * 7.5f, 14.99999f);
    int x0 = (int)gx;
    int y0 = (int)gy;
    int z0 = (int)gz;
    float fx = gx - (float)x0;
    float fy = gy - (float)y0;
    float fz = gz - (float)z0;

    const float4* T = g_tmpl + (((k * MV + z0) * MV + y0) * MV + x0);
    float4 c000 = __ldg(T + 0),   c001 = __ldg(T + 1);
    float4 c010 = __ldg(T + 16),  c011 = __ldg(T + 17);
    float4 c100 = __ldg(T + 256), c101 = __ldg(T + 257);
    float4 c110 = __ldg(T + 272), c111 = __ldg(T + 273);

    float wz0 = 1.0f - fz, wy0 = 1.0f - fy, wx0 = 1.0f - fx;
    float w000 = wz0 * wy0 * wx0, w001 = wz0 * wy0 * fx;
    float w010 = wz0 * fy * wx0,  w011 = wz0 * fy * fx;
    float w100 = fz * wy0 * wx0,  w101 = fz * wy0 * fx;
    float w110 = fz * fy * wx0,   w111 = fz * fy * fx;

    s[0] = fmaf(c000.x, w000, s[0]); s[1] = fmaf(c000.y, w000, s[1]);
    s[2] = fmaf(c000.z, w000, s[2]); s[3] = fmaf(c000.w, w000, s[3]);
    s[0] = fmaf(c001.x, w001, s[0]); s[1] = fmaf(c001.y, w001, s[1]);
    s[2] = fmaf(c001.z, w001, s[2]); s[3] = fmaf(c001.w, w001, s[3]);
    s[0] = fmaf(c010.x, w010, s[0]); s[1] = fmaf(c010.y, w010, s[1]);
    s[2] = fmaf(c010.z, w010, s[2]); s[3] = fmaf(c010.w, w010, s[3]);
    s[0] = fmaf(c011.x, w011, s[0]); s[1] = fmaf(c011.y, w011, s[1]);
    s[2] = fmaf(c011.z, w011, s[2]); s[3] = fmaf(c011.w, w011, s[3]);
    s[0] = fmaf(c100.x, w100, s[0]); s[1] = fmaf(c100.y, w100, s[1]);
    s[2] = fmaf(c100.z, w100, s[2]); s[3] = fmaf(c100.w, w100, s[3]);
    s[0] = fmaf(c101.x, w101, s[0]); s[1] = fmaf(c101.y, w101, s[1]);
    s[2] = fmaf(c101.z, w101, s[2]); s[3] = fmaf(c101.w, w101, s[3]);
    s[0] = fmaf(c110.x, w110, s[0]); s[1] = fmaf(c110.y, w110, s[1]);
    s[2] = fmaf(c110.z, w110, s[2]); s[3] = fmaf(c110.w, w110, s[3]);
    s[0] = fmaf(c111.x, w111, s[0]); s[1] = fmaf(c111.y, w111, s[1]);
    s[2] = fmaf(c111.z, w111, s[2]); s[3] = fmaf(c111.w, w111, s[3]);
}

// Exact OBB slab test (lo/ld computed and discarded — cull only).
__device__ __forceinline__ bool obb_test(
    const float* __restrict__ P,
    float ox, float oy, float oz,
    float dx, float dy, float dz,
    float tmin, float tmax)
{
    float rx = ox - P[9], ry = oy - P[10], rz = oz - P[11];
    float lo3[3], ld3[3];
    lo3[0] = (rx * P[0] + ry * P[3] + rz * P[6]) * P[12];
    lo3[1] = (rx * P[1] + ry * P[4] + rz * P[7]) * P[13];
    lo3[2] = (rx * P[2] + ry * P[5] + rz * P[8]) * P[14];
    ld3[0] = (dx * P[0] + dy * P[3] + dz * P[6]) * P[12];
    ld3[1] = (dx * P[1] + dy * P[4] + dz * P[7]) * P[13];
    ld3[2] = (dx * P[2] + dy * P[5] + dz * P[8]) * P[14];
    float t0 = tmin, t1 = tmax;
#pragma unroll
    for (int a = 0; a < 3; a++) {
        float lo = lo3[a], ld = ld3[a];
        if (fabsf(ld) > 1e-12f) {
            float inv = 1.0f / ld;
            float ta = (-1.0f - lo) * inv;
            float tb = ( 1.0f - lo) * inv;
            t0 = fmaxf(t0, fminf(ta, tb));
            t1 = fminf(t1, fmaxf(ta, tb));
        } else if (fabsf(lo) >= 1.0f) {
            return false;
        }
    }
    return t0 <= t1;
}

// One warp per ray; lane owns steps {lane, lane+32}.
// 4 warps/block; rays strided by 16384 so a block's rays are 64 image-rows apart
// (hot central rays spread across many blocks/SMs instead of stacking).
__global__ __launch_bounds__(128) void march_kernel(
    const float* __restrict__ raypos,
    const float* __restrict__ raydir,
    const float* __restrict__ tminmax,
    float* __restrict__ out)
{
    __shared__ float sP[KK * 16];
    for (int i = threadIdx.x; i < KK * 16; i += 128) sP[i] = g_prim[i];
    __syncthreads();

    int lane = threadIdx.x & 31;
    int warpId = threadIdx.x >> 5;
    int r = warpId * 16384 + blockIdx.x;  // strided ray assignment

    float ox = raypos[r * 3 + 0], oy = raypos[r * 3 + 1], oz = raypos[r * 3 + 2];
    float dx = raydir[r * 3 + 0], dy = raydir[r * 3 + 1], dz = raydir[r * 3 + 2];
    float tmin = tminmax[r * 2 + 0], tmax = tminmax[r * 2 + 1];

    // Cooperative exact-OBB cull: lane tests prims {lane, lane+32}
    bool a0 = obb_test(sP + lane * 16,        ox, oy, oz, dx, dy, dz, tmin, tmax);
    bool a1 = obb_test(sP + (lane + 32) * 16, ox, oy, oz, dx, dy, dz, tmin, tmax);
    unsigned m0 = __ballot_sync(0xFFFFFFFFu, a0);
    unsigned m1 = __ballot_sync(0xFFFFFFFFu, a1);
    unsigned long long mask = (unsigned long long)m0 |
                              ((unsigned long long)m1 << 32);

    // Two sample points per lane
    float t0 = fmaf((float)lane + 0.5f,  DTST, tmin);
    float t1 = fmaf((float)lane + 32.5f, DTST, tmin);
    float p0x = fmaf(t0, dx, ox), p0y = fmaf(t0, dy, oy), p0z = fmaf(t0, dz, oz);
    float p1x = fmaf(t1, dx, ox), p1y = fmaf(t1, dy, oy), p1z = fmaf(t1, dz, oz);

    float s0[4] = {0.f, 0.f, 0.f, 0.f};
    float s1[4] = {0.f, 0.f, 0.f, 0.f};

    while (mask) {
        int k = __ffsll(mask) - 1;
        mask &= mask - 1;
        const float* P = sP + k * 16;
        eval_prim(P, k, p0x, p0y, p0z, s0);
        eval_prim(P, k, p1x, p1y, p1z, s1);
    }

    // Alpha compositing via prefix sum: alpha_i = min(1, sum_{j<=i} d_j)
    float d0 = (t0 < tmax) ? s0[3] * DTST : 0.f;
    float d1 = (t1 < tmax) ? s1[3] * DTST : 0.f;

    float c0 = d0;
#pragma unroll
    for (int off = 1; off < 32; off <<= 1) {
        float v = __shfl_up_sync(0xFFFFFFFFu, c0, off);
        if (lane >= off) c0 += v;
    }
    float tot0 = __shfl_sync(0xFFFFFFFFu, c0, 31);
    float c1 = d1;
#pragma unroll
    for (int off = 1; off < 32; off <<= 1) {
        float v = __shfl_up_sync(0xFFFFFFFFu, c1, off);
        if (lane >= off) c1 += v;
    }
    float S0 = c0;            // inclusive prefix at step lane
    float S1 = tot0 + c1;     // inclusive prefix at step lane+32
    float contrib0 = fminf(1.f, S0) - fminf(1.f, S0 - d0);
    float contrib1 = fminf(1.f, S1) - fminf(1.f, S1 - d1);

    float rgbx = s0[0] * contrib0 + s1[0] * contrib1;
    float rgby = s0[1] * contrib0 + s1[1] * contrib1;
    float rgbz = s0[2] * contrib0 + s1[2] * contrib1;

#pragma unroll
    for (int off = 16; off > 0; off >>= 1) {
        rgbx += __shfl_xor_sync(0xFFFFFFFFu, rgbx, off);
        rgby += __shfl_xor_sync(0xFFFFFFFFu, rgby, off);
        rgbz += __shfl_xor_sync(0xFFFFFFFFu, rgbz, off);
    }
    float alphaF = fminf(1.f, __shfl_sync(0xFFFFFFFFu, S1, 31));

    if (lane == 0) {
        const int HWsz = HH * WW;
        out[0 * HWsz + r] = rgbx;
        out[1 * HWsz + r] = rgby;
        out[2 * HWsz + r] = rgbz;
        out[3 * HWsz + r] = alphaF;
        out[4 * HWsz + r] = rgbx;
        out[5 * HWsz + r] = rgby;
        out[6 * HWsz + r] = rgbz;
        out[7 * HWsz + r] = alphaF;
    }
}

extern "C" void kernel_launch(void* const* d_in, const int* in_sizes, int n_in,
                              void* d_out, int out_size) {
    const float* raypos    = (const float*)d_in[0];
    const float* raydir    = (const float*)d_in[1];
    const float* tminmax   = (const float*)d_in[2];
    const float* primpos   = (const float*)d_in[3];
    const float* primrot   = (const float*)d_in[4];
    const float* primscale = (const float*)d_in[5];
    const float* primrgba  = (const float*)d_in[6];
    float* out = (float*)d_out;

    pack_prep_kernel<<<1025, 256>>>(primrgba, primpos, primrot, primscale);
    march_kernel<<<HH * WW / 4, 128>>>(raypos, raydir, tminmax, out);
}

// round 7
// speedup vs baseline: 1.3362x; 1.3362x over previous
#include <cuda_runtime.h>
#include <cuda_fp16.h>

#define HH 256
#define WW 256
#define KK 64
#define MV 16
#define NSTEPS 64
#define VOLR 256.0f
#define DTST (1.0f/256.0f)

// Template [k][z][y][x] -> half4 packed as uint2 {half2(r,g), half2(b,a)} : 2 MB
__device__ uint2 g_tmpl[KK * MV * MV * MV];
// Per-prim params as 4 float4 per prim:
//  A = {R00,R01,R02,R10}, B = {R11,R12,R20,R21}, C = {R22,px,py,pz}, D = {sx,sy,sz,0}
__device__ float4 g_prim[KK * 4];

// Blocks 0..1023: repack template to fp16. Block 1024: prep prim params.
__global__ void pack_prep_kernel(const float* __restrict__ primrgba,
                                 const float* __restrict__ primpos,
                                 const float* __restrict__ primrot,
                                 const float* __restrict__ primscale) {
    int b = blockIdx.x;
    if (b < 1024) {
        int idx = b * 256 + threadIdx.x;
        int k = idx >> 12;
        int v = idx & 4095;
        const float* base = primrgba + (size_t)k * 4 * 4096 + v;
        float r = base[0];
        float g = base[4096];
        float bl = base[8192];
        float a = base[12288];
        __half2 rg = __floats2half2_rn(r, g);
        __half2 ba = __floats2half2_rn(bl, a);
        uint2 val;
        val.x = *reinterpret_cast<unsigned*>(&rg);
        val.y = *reinterpret_cast<unsigned*>(&ba);
        g_tmpl[idx] = val;
    } else {
        int k = threadIdx.x;
        if (k >= KK) return;
        float R[9];
#pragma unroll
        for (int i = 0; i < 9; i++) R[i] = primrot[k * 9 + i];
        float4 A = {R[0], R[1], R[2], R[3]};
        float4 Bv = {R[4], R[5], R[6], R[7]};
        float4 Cv = {R[8],
                     primpos[k * 3 + 0] / VOLR,
                     primpos[k * 3 + 1] / VOLR,
                     primpos[k * 3 + 2] / VOLR};
        float4 Dv = {primscale[k * 3 + 0],
                     primscale[k * 3 + 1],
                     primscale[k * 3 + 2], 0.f};
        g_prim[k * 4 + 0] = A;
        g_prim[k * 4 + 1] = Bv;
        g_prim[k * 4 + 2] = Cv;
        g_prim[k * 4 + 3] = Dv;
    }
}

// Full per-point evaluation: transform + inside test + fp16 trilinear gather.
__device__ __forceinline__ void eval_prim(
    const float4 A, const float4 B, const float4 C, const float4 D, int k,
    float px, float py, float pz, float s[4])
{
    float rx = px - C.y, ry = py - C.z, rz = pz - C.w;
    float lx = (rx * A.x + ry * A.w + rz * B.z) * D.x;
    float ly = (rx * A.y + ry * B.x + rz * B.w) * D.y;
    float lz = (rx * A.z + ry * B.y + rz * C.x) * D.z;
    if (!(fabsf(lx) < 1.0f && fabsf(ly) < 1.0f && fabsf(lz) < 1.0f)) return;

    float gx = fminf((lx + 1.0f) * 7.5f, 14.99999f);
    float gy = fminf((ly + 1.0f) * 7.5f, 14.99999f);
    float gz = fminf((lz + 1.0f) * 7.5f, 14.99999f);
    int x0 = (int)gx;
    int y0 = (int)gy;
    int z0 = (int)gz;
    float fx = gx - (float)x0;
    float fy = gy - (float)y0;
    float fz = gz - (float)z0;

    const uint2* T = g_tmpl + (((k * MV + z0) * MV + y0) * MV + x0);
    uint2 u000 = __ldg(T + 0),   u001 = __ldg(T + 1);
    uint2 u010 = __ldg(T + 16),  u011 = __ldg(T + 17);
    uint2 u100 = __ldg(T + 256), u101 = __ldg(T + 257);
    uint2 u110 = __ldg(T + 272), u111 = __ldg(T + 273);

    float wz0 = 1.0f - fz, wy0 = 1.0f - fy, wx0 = 1.0f - fx;
    float w000 = wz0 * wy0 * wx0, w001 = wz0 * wy0 * fx;
    float w010 = wz0 * fy * wx0,  w011 = wz0 * fy * fx;
    float w100 = fz * wy0 * wx0,  w101 = fz * wy0 * fx;
    float w110 = fz * fy * wx0,   w111 = fz * fy * fx;

#define ACC(u, w)                                                         \
    {                                                                     \
        float2 rg = __half22float2(*reinterpret_cast<const __half2*>(&(u).x)); \
        float2 ba = __half22float2(*reinterpret_cast<const __half2*>(&(u).y)); \
        s[0] = fmaf(rg.x, (w), s[0]);                                     \
        s[1] = fmaf(rg.y, (w), s[1]);                                     \
        s[2] = fmaf(ba.x, (w), s[2]);                                     \
        s[3] = fmaf(ba.y, (w), s[3]);                                     \
    }
    ACC(u000, w000) ACC(u001, w001) ACC(u010, w010) ACC(u011, w011)
    ACC(u100, w100) ACC(u101, w101) ACC(u110, w110) ACC(u111, w111)
#undef ACC
}

// Exact OBB slab test (cull only).
__device__ __forceinline__ bool obb_test(
    const float4* __restrict__ sP4, int k,
    float ox, float oy, float oz,
    float dx, float dy, float dz,
    float tmin, float tmax)
{
    float4 A = sP4[k * 4 + 0];
    float4 B = sP4[k * 4 + 1];
    float4 C = sP4[k * 4 + 2];
    float4 D = sP4[k * 4 + 3];
    float rx = ox - C.y, ry = oy - C.z, rz = oz - C.w;
    float lo3[3], ld3[3];
    lo3[0] = (rx * A.x + ry * A.w + rz * B.z) * D.x;
    lo3[1] = (rx * A.y + ry * B.x + rz * B.w) * D.y;
    lo3[2] = (rx * A.z + ry * B.y + rz * C.x) * D.z;
    ld3[0] = (dx * A.x + dy * A.w + dz * B.z) * D.x;
    ld3[1] = (dx * A.y + dy * B.x + dz * B.w) * D.y;
    ld3[2] = (dx * A.z + dy * B.y + dz * C.x) * D.z;
    float t0 = tmin, t1 = tmax;
#pragma unroll
    for (int a = 0; a < 3; a++) {
        float lo = lo3[a], ld = ld3[a];
        if (fabsf(ld) > 1e-12f) {
            float inv = 1.0f / ld;
            float ta = (-1.0f - lo) * inv;
            float tb = ( 1.0f - lo) * inv;
            t0 = fmaxf(t0, fminf(ta, tb));
            t1 = fminf(t1, fmaxf(ta, tb));
        } else if (fabsf(lo) >= 1.0f) {
            return false;
        }
    }
    return t0 <= t1;
}

// One warp per ray; lane owns steps {lane, lane+32}. 8 consecutive rays per block (R3 layout).
__global__ __launch_bounds__(256) void march_kernel(
    const float* __restrict__ raypos,
    const float* __restrict__ raydir,
    const float* __restrict__ tminmax,
    float* __restrict__ out)
{
    __shared__ float4 sP4[KK * 4];
    for (int i = threadIdx.x; i < KK * 4; i += 256) sP4[i] = g_prim[i];
    __syncthreads();

    int lane = threadIdx.x & 31;
    int warpId = threadIdx.x >> 5;
    int r = blockIdx.x * 8 + warpId;  // consecutive rays (L1 template locality)

    float ox = raypos[r * 3 + 0], oy = raypos[r * 3 + 1], oz = raypos[r * 3 + 2];
    float dx = raydir[r * 3 + 0], dy = raydir[r * 3 + 1], dz = raydir[r * 3 + 2];
    float tmin = tminmax[r * 2 + 0], tmax = tminmax[r * 2 + 1];

    // Cooperative exact-OBB cull: lane tests prims {lane, lane+32}
    bool a0 = obb_test(sP4, lane,      ox, oy, oz, dx, dy, dz, tmin, tmax);
    bool a1 = obb_test(sP4, lane + 32, ox, oy, oz, dx, dy, dz, tmin, tmax);
    unsigned m0 = __ballot_sync(0xFFFFFFFFu, a0);
    unsigned m1 = __ballot_sync(0xFFFFFFFFu, a1);
    unsigned long long mask = (unsigned long long)m0 |
                              ((unsigned long long)m1 << 32);

    // Two sample points per lane
    float t0 = fmaf((float)lane + 0.5f,  DTST, tmin);
    float t1 = fmaf((float)lane + 32.5f, DTST, tmin);
    float p0x = fmaf(t0, dx, ox), p0y = fmaf(t0, dy, oy), p0z = fmaf(t0, dz, oz);
    float p1x = fmaf(t1, dx, ox), p1y = fmaf(t1, dy, oy), p1z = fmaf(t1, dz, oz);

    float s0[4] = {0.f, 0.f, 0.f, 0.f};
    float s1[4] = {0.f, 0.f, 0.f, 0.f};

    while (mask) {
        int k = __ffsll(mask) - 1;   // warp-uniform
        mask &= mask - 1;
        float4 A = sP4[k * 4 + 0];   // LDS.128 broadcast x4
        float4 B = sP4[k * 4 + 1];
        float4 C = sP4[k * 4 + 2];
        float4 D = sP4[k * 4 + 3];
        eval_prim(A, B, C, D, k, p0x, p0y, p0z, s0);
        eval_prim(A, B, C, D, k, p1x, p1y, p1z, s1);
    }

    // Alpha compositing via prefix sum: alpha_i = min(1, sum_{j<=i} d_j)
    float d0 = (t0 < tmax) ? s0[3] * DTST : 0.f;
    float d1 = (t1 < tmax) ? s1[3] * DTST : 0.f;

    float c0 = d0;
#pragma unroll
    for (int off = 1; off < 32; off <<= 1) {
        float v = __shfl_up_sync(0xFFFFFFFFu, c0, off);
        if (lane >= off) c0 += v;
    }
    float tot0 = __shfl_sync(0xFFFFFFFFu, c0, 31);
    float c1 = d1;
#pragma unroll
    for (int off = 1; off < 32; off <<= 1) {
        float v = __shfl_up_sync(0xFFFFFFFFu, c1, off);
        if (lane >= off) c1 += v;
    }
    float S0 = c0;            // inclusive prefix at step lane
    float S1 = tot0 + c1;     // inclusive prefix at step lane+32
    float contrib0 = fminf(1.f, S0) - fminf(1.f, S0 - d0);
    float contrib1 = fminf(1.f, S1) - fminf(1.f, S1 - d1);

    float rgbx = s0[0] * contrib0 + s1[0] * contrib1;
    float rgby = s0[1] * contrib0 + s1[1] * contrib1;
    float rgbz = s0[2] * contrib0 + s1[2] * contrib1;

#pragma unroll
    for (int off = 16; off > 0; off >>= 1) {
        rgbx += __shfl_xor_sync(0xFFFFFFFFu, rgbx, off);
        rgby += __shfl_xor_sync(0xFFFFFFFFu, rgby, off);
        rgbz += __shfl_xor_sync(0xFFFFFFFFu, rgbz, off);
    }
    float alphaF = fminf(1.f, __shfl_sync(0xFFFFFFFFu, S1, 31));

    if (lane == 0) {
        const int HWsz = HH * WW;
        out[0 * HWsz + r] = rgbx;
        out[1 * HWsz + r] = rgby;
        out[2 * HWsz + r] = rgbz;
        out[3 * HWsz + r] = alphaF;
        out[4 * HWsz + r] = rgbx;
        out[5 * HWsz + r] = rgby;
        out[6 * HWsz + r] = rgbz;
        out[7 * HWsz + r] = alphaF;
    }
}

extern "C" void kernel_launch(void* const* d_in, const int* in_sizes, int n_in,
                              void* d_out, int out_size) {
    const float* raypos    = (const float*)d_in[0];
    const float* raydir    = (const float*)d_in[1];
    const float* tminmax   = (const float*)d_in[2];
    const float* primpos   = (const float*)d_in[3];
    const float* primrot   = (const float*)d_in[4];
    const float* primscale = (const float*)d_in[5];
    const float* primrgba  = (const float*)d_in[6];
    float* out = (float*)d_out;

    pack_prep_kernel<<<1025, 256>>>(primrgba, primpos, primrot, primscale);
    march_kernel<<<HH * WW / 8, 256>>>(raypos, raydir, tminmax, out);
}

// round 8
// speedup vs baseline: 1.4404x; 1.0780x over previous
#include <cuda_runtime.h>
#include <cuda_fp16.h>

#define HH 256
#define WW 256
#define KK 64
#define MV 16
#define NSTEPS 64
#define VOLR 256.0f
#define DTST (1.0f/256.0f)

// Template with paired x-cells: entry [k][z][y][x] holds {cell(x), cell(x+1)} as
// uint4 { half2(r,g)@x, half2(b,a)@x, half2(r,g)@x+1, half2(b,a)@x+1 } : 4 MB
__device__ uint4 g_tmpl[KK * MV * MV * MV];
// Per-prim params as 4 float4 per prim:
//  A = {R00,R01,R02,R10}, B = {R11,R12,R20,R21}, C = {R22,px,py,pz}, D = {sx,sy,sz,0}
__device__ float4 g_prim[KK * 4];

// Blocks 0..1023: repack template to paired fp16. Block 1024: prep prim params.
__global__ void pack_prep_kernel(const float* __restrict__ primrgba,
                                 const float* __restrict__ primpos,
                                 const float* __restrict__ primrot,
                                 const float* __restrict__ primscale) {
    int b = blockIdx.x;
    if (b < 1024) {
        int idx = b * 256 + threadIdx.x;
        int k = idx >> 12;
        int v = idx & 4095;          // z*256 + y*16 + x
        int x = v & 15;
        int v1 = (x < 15) ? v + 1 : v;  // clamp (x=15 entry never read with x1 offset)
        const float* base = primrgba + (size_t)k * 4 * 4096;
        __half2 rg0 = __floats2half2_rn(base[v], base[4096 + v]);
        __half2 ba0 = __floats2half2_rn(base[8192 + v], base[12288 + v]);
        __half2 rg1 = __floats2half2_rn(base[v1], base[4096 + v1]);
        __half2 ba1 = __floats2half2_rn(base[8192 + v1], base[12288 + v1]);
        uint4 val;
        val.x = *reinterpret_cast<unsigned*>(&rg0);
        val.y = *reinterpret_cast<unsigned*>(&ba0);
        val.z = *reinterpret_cast<unsigned*>(&rg1);
        val.w = *reinterpret_cast<unsigned*>(&ba1);
        g_tmpl[idx] = val;
    } else {
        int k = threadIdx.x;
        if (k >= KK) return;
        float R[9];
#pragma unroll
        for (int i = 0; i < 9; i++) R[i] = primrot[k * 9 + i];
        float4 A = {R[0], R[1], R[2], R[3]};
        float4 Bv = {R[4], R[5], R[6], R[7]};
        float4 Cv = {R[8],
                     primpos[k * 3 + 0] / VOLR,
                     primpos[k * 3 + 1] / VOLR,
                     primpos[k * 3 + 2] / VOLR};
        float4 Dv = {primscale[k * 3 + 0],
                     primscale[k * 3 + 1],
                     primscale[k * 3 + 2], 0.f};
        g_prim[k * 4 + 0] = A;
        g_prim[k * 4 + 1] = Bv;
        g_prim[k * 4 + 2] = Cv;
        g_prim[k * 4 + 3] = Dv;
    }
}

// Full per-point evaluation: transform + inside test + paired fp16 trilinear gather.
__device__ __forceinline__ void eval_prim(
    const float4 A, const float4 B, const float4 C, const float4 D, int k,
    float px, float py, float pz, float s[4])
{
    float rx = px - C.y, ry = py - C.z, rz = pz - C.w;
    float lx = (rx * A.x + ry * A.w + rz * B.z) * D.x;
    float ly = (rx * A.y + ry * B.x + rz * B.w) * D.y;
    float lz = (rx * A.z + ry * B.y + rz * C.x) * D.z;
    if (!(fabsf(lx) < 1.0f && fabsf(ly) < 1.0f && fabsf(lz) < 1.0f)) return;

    float gx = fminf((lx + 1.0f) * 7.5f, 14.99999f);
    float gy = fminf((ly + 1.0f) * 7.5f, 14.99999f);
    float gz = fminf((lz + 1.0f) * 7.5f, 14.99999f);
    int x0 = (int)gx;
    int y0 = (int)gy;
    int z0 = (int)gz;
    float fx = gx - (float)x0;
    float fy = gy - (float)y0;
    float fz = gz - (float)z0;

    // 4 aligned LDG.128: each holds corners (x0, x0+1) for one (z,y)
    const uint4* T = g_tmpl + (((k * MV + z0) * MV + y0) * MV + x0);
    uint4 q00 = __ldg(T + 0);    // z0,   y0
    uint4 q01 = __ldg(T + 16);   // z0,   y0+1
    uint4 q10 = __ldg(T + 256);  // z0+1, y0
    uint4 q11 = __ldg(T + 272);  // z0+1, y0+1

    float wz0 = 1.0f - fz, wy0 = 1.0f - fy, wx0 = 1.0f - fx;
    float w000 = wz0 * wy0 * wx0, w001 = wz0 * wy0 * fx;
    float w010 = wz0 * fy * wx0,  w011 = wz0 * fy * fx;
    float w100 = fz * wy0 * wx0,  w101 = fz * wy0 * fx;
    float w110 = fz * fy * wx0,   w111 = fz * fy * fx;

#define ACC2(q, wA, wB)                                                   \
    {                                                                     \
        float2 rgA = __half22float2(*reinterpret_cast<const __half2*>(&(q).x)); \
        float2 baA = __half22float2(*reinterpret_cast<const __half2*>(&(q).y)); \
        float2 rgB = __half22float2(*reinterpret_cast<const __half2*>(&(q).z)); \
        float2 baB = __half22float2(*reinterpret_cast<const __half2*>(&(q).w)); \
        s[0] = fmaf(rgA.x, (wA), s[0]); s[1] = fmaf(rgA.y, (wA), s[1]);   \
        s[2] = fmaf(baA.x, (wA), s[2]); s[3] = fmaf(baA.y, (wA), s[3]);   \
        s[0] = fmaf(rgB.x, (wB), s[0]); s[1] = fmaf(rgB.y, (wB), s[1]);   \
        s[2] = fmaf(baB.x, (wB), s[2]); s[3] = fmaf(baB.y, (wB), s[3]);   \
    }
    ACC2(q00, w000, w001)
    ACC2(q01, w010, w011)
    ACC2(q10, w100, w101)
    ACC2(q11, w110, w111)
#undef ACC2
}

// Exact OBB slab test (cull only).
__device__ __forceinline__ bool obb_test(
    const float4* __restrict__ sP4, int k,
    float ox, float oy, float oz,
    float dx, float dy, float dz,
    float tmin, float tmax)
{
    float4 A = sP4[k * 4 + 0];
    float4 B = sP4[k * 4 + 1];
    float4 C = sP4[k * 4 + 2];
    float4 D = sP4[k * 4 + 3];
    float rx = ox - C.y, ry = oy - C.z, rz = oz - C.w;
    float lo3[3], ld3[3];
    lo3[0] = (rx * A.x + ry * A.w + rz * B.z) * D.x;
    lo3[1] = (rx * A.y + ry * B.x + rz * B.w) * D.y;
    lo3[2] = (rx * A.z + ry * B.y + rz * C.x) * D.z;
    ld3[0] = (dx * A.x + dy * A.w + dz * B.z) * D.x;
    ld3[1] = (dx * A.y + dy * B.x + dz * B.w) * D.y;
    ld3[2] = (dx * A.z + dy * B.y + dz * C.x) * D.z;
    float t0 = tmin, t1 = tmax;
#pragma unroll
    for (int a = 0; a < 3; a++) {
        float lo = lo3[a], ld = ld3[a];
        if (fabsf(ld) > 1e-12f) {
            float inv = 1.0f / ld;
            float ta = (-1.0f - lo) * inv;
            float tb = ( 1.0f - lo) * inv;
            t0 = fmaxf(t0, fminf(ta, tb));
            t1 = fminf(t1, fmaxf(ta, tb));
        } else if (fabsf(lo) >= 1.0f) {
            return false;
        }
    }
    return t0 <= t1;
}

// One warp per ray; lane owns steps {lane, lane+32}. 8 consecutive rays per block.
__global__ __launch_bounds__(256) void march_kernel(
    const float* __restrict__ raypos,
    const float* __restrict__ raydir,
    const float* __restrict__ tminmax,
    float* __restrict__ out)
{
    __shared__ float4 sP4[KK * 4];
    for (int i = threadIdx.x; i < KK * 4; i += 256) sP4[i] = g_prim[i];
    __syncthreads();

    int lane = threadIdx.x & 31;
    int warpId = threadIdx.x >> 5;
    int r = blockIdx.x * 8 + warpId;  // consecutive rays (L1 template locality)

    float ox = raypos[r * 3 + 0], oy = raypos[r * 3 + 1], oz = raypos[r * 3 + 2];
    float dx = raydir[r * 3 + 0], dy = raydir[r * 3 + 1], dz = raydir[r * 3 + 2];
    float tmin = tminmax[r * 2 + 0], tmax = tminmax[r * 2 + 1];

    // Cooperative exact-OBB cull: lane tests prims {lane, lane+32}
    bool a0 = obb_test(sP4, lane,      ox, oy, oz, dx, dy, dz, tmin, tmax);
    bool a1 = obb_test(sP4, lane + 32, ox, oy, oz, dx, dy, dz, tmin, tmax);
    unsigned m0 = __ballot_sync(0xFFFFFFFFu, a0);
    unsigned m1 = __ballot_sync(0xFFFFFFFFu, a1);
    unsigned long long mask = (unsigned long long)m0 |
                              ((unsigned long long)m1 << 32);

    // Two sample points per lane
    float t0 = fmaf((float)lane + 0.5f,  DTST, tmin);
    float t1 = fmaf((float)lane + 32.5f, DTST, tmin);
    float p0x = fmaf(t0, dx, ox), p0y = fmaf(t0, dy, oy), p0z = fmaf(t0, dz, oz);
    float p1x = fmaf(t1, dx, ox), p1y = fmaf(t1, dy, oy), p1z = fmaf(t1, dz, oz);

    float s0[4] = {0.f, 0.f, 0.f, 0.f};
    float s1[4] = {0.f, 0.f, 0.f, 0.f};

    while (mask) {
        int k = __ffsll(mask) - 1;   // warp-uniform
        mask &= mask - 1;
        float4 A = sP4[k * 4 + 0];   // LDS.128 broadcast x4
        float4 B = sP4[k * 4 + 1];
        float4 C = sP4[k * 4 + 2];
        float4 D = sP4[k * 4 + 3];
        eval_prim(A, B, C, D, k, p0x, p0y, p0z, s0);
        eval_prim(A, B, C, D, k, p1x, p1y, p1z, s1);
    }

    // Alpha compositing via prefix sum: alpha_i = min(1, sum_{j<=i} d_j)
    float d0 = (t0 < tmax) ? s0[3] * DTST : 0.f;
    float d1 = (t1 < tmax) ? s1[3] * DTST : 0.f;

    float c0 = d0;
#pragma unroll
    for (int off = 1; off < 32; off <<= 1) {
        float v = __shfl_up_sync(0xFFFFFFFFu, c0, off);
        if (lane >= off) c0 += v;
    }
    float tot0 = __shfl_sync(0xFFFFFFFFu, c0, 31);
    float c1 = d1;
#pragma unroll
    for (int off = 1; off < 32; off <<= 1) {
        float v = __shfl_up_sync(0xFFFFFFFFu, c1, off);
        if (lane >= off) c1 += v;
    }
    float S0 = c0;            // inclusive prefix at step lane
    float S1 = tot0 + c1;     // inclusive prefix at step lane+32
    float contrib0 = fminf(1.f, S0) - fminf(1.f, S0 - d0);
    float contrib1 = fminf(1.f, S1) - fminf(1.f, S1 - d1);

    float rgbx = s0[0] * contrib0 + s1[0] * contrib1;
    float rgby = s0[1] * contrib0 + s1[1] * contrib1;
    float rgbz = s0[2] * contrib0 + s1[2] * contrib1;

#pragma unroll
    for (int off = 16; off > 0; off >>= 1) {
        rgbx += __shfl_xor_sync(0xFFFFFFFFu, rgbx, off);
        rgby += __shfl_xor_sync(0xFFFFFFFFu, rgby, off);
        rgbz += __shfl_xor_sync(0xFFFFFFFFu, rgbz, off);
    }
    float alphaF = fminf(1.f, __shfl_sync(0xFFFFFFFFu, S1, 31));

    if (lane == 0) {
        const int HWsz = HH * WW;
        out[0 * HWsz + r] = rgbx;
        out[1 * HWsz + r] = rgby;
        out[2 * HWsz + r] = rgbz;
        out[3 * HWsz + r] = alphaF;
        out[4 * HWsz + r] = rgbx;
        out[5 * HWsz + r] = rgby;
        out[6 * HWsz + r] = rgbz;
        out[7 * HWsz + r] = alphaF;
    }
}

extern "C" void kernel_launch(void* const* d_in, const int* in_sizes, int n_in,
                              void* d_out, int out_size) {
    const float* raypos    = (const float*)d_in[0];
    const float* raydir    = (const float*)d_in[1];
    const float* tminmax   = (const float*)d_in[2];
    const float* primpos   = (const float*)d_in[3];
    const float* primrot   = (const float*)d_in[4];
    const float* primscale = (const float*)d_in[5];
    const float* primrgba  = (const float*)d_in[6];
    float* out = (float*)d_out;

    pack_prep_kernel<<<1025, 256>>>(primrgba, primpos, primrot, primscale);
    march_kernel<<<HH * WW / 8, 256>>>(raypos, raydir, tminmax, out);
}